// round 5
// baseline (speedup 1.0000x reference)
#include <cuda_runtime.h>
#include <cuda_fp16.h>
#include <math.h>
#include <stdint.h>

#define NB 4
#define NC 512
#define NT 1024
#define NHEADS 8
#define NHD 64
#define EPS_IN 1e-5f

// ---------------- device scratch ----------------
__device__ float g_q[NB * NC * NT];
__device__ float g_k[NB * NC * NT];
__device__ float g_v[NB * NC * NT];
__device__ __half g_vh[NB * NC * NT];                       // fp16 shadow of v
__device__ float g_attn[(size_t)NB * NHEADS * NT * NT];     // raw logits fp32 134MB
__device__ __half g_ph[(size_t)NB * NHEADS * NT * NT];      // softmax probs fp16 67MB
__device__ float g_out[NB * NHEADS * NT * NHD];             // == [b][t][c]
__device__ float g_vsum[NB * NC];
__device__ float g_rowsq[NB * NHEADS * NT];
__device__ float g_alpha[32];
__device__ float g_betac[32];

// ---------------- mma helpers ----------------
__device__ __forceinline__ uint32_t f2tf(float f) {
    uint32_t u;
    asm("cvt.rna.tf32.f32 %0, %1;" : "=r"(u) : "f"(f));
    return u;
}
__device__ __forceinline__ void mma8(float* c, const uint32_t* a, const uint32_t* b) {
    asm volatile("mma.sync.aligned.m16n8k8.row.col.f32.tf32.tf32.f32 "
        "{%0,%1,%2,%3}, {%4,%5,%6,%7}, {%8,%9}, {%0,%1,%2,%3};\n"
        : "+f"(c[0]), "+f"(c[1]), "+f"(c[2]), "+f"(c[3])
        : "r"(a[0]), "r"(a[1]), "r"(a[2]), "r"(a[3]), "r"(b[0]), "r"(b[1]));
}
__device__ __forceinline__ void mma16h(float* c, const uint32_t* a, const uint32_t* b) {
    asm volatile("mma.sync.aligned.m16n8k16.row.col.f32.f16.f16.f32 "
        "{%0,%1,%2,%3}, {%4,%5,%6,%7}, {%8,%9}, {%0,%1,%2,%3};\n"
        : "+f"(c[0]), "+f"(c[1]), "+f"(c[2]), "+f"(c[3])
        : "r"(a[0]), "r"(a[1]), "r"(a[2]), "r"(a[3]), "r"(b[0]), "r"(b[1]));
}

// ============ Kernel 1: QKV. out[o,t] = sum_c W[o,c] x[c,t] ============
__global__ __launch_bounds__(256) void qkv_tf32(const float* __restrict__ x,
                                                const float* __restrict__ wq,
                                                const float* __restrict__ wk,
                                                const float* __restrict__ wv) {
    int z = blockIdx.z;
    int b = z / 3, which = z - b * 3;
    const float* W = (which == 0) ? wq : (which == 1) ? wk : wv;
    float* out = ((which == 0) ? g_q : (which == 1) ? g_k : g_v) + (size_t)b * NC * NT;
    const float* X = x + (size_t)b * NC * NT;

    int oBase = blockIdx.y * 128;
    int tBase = blockIdx.x * 128;

    __shared__ uint32_t As[128][36];   // [o][c]
    __shared__ uint32_t Bs[128][36];   // [t][c]

    int tid = threadIdx.x, lane = tid & 31, wid = tid >> 5;
    int wm = wid >> 2, wn = wid & 3;
    int lr = lane >> 2, lk = lane & 3;

    float acc[4][4][4];
#pragma unroll
    for (int mi = 0; mi < 4; mi++)
#pragma unroll
        for (int nj = 0; nj < 4; nj++)
#pragma unroll
            for (int ci = 0; ci < 4; ci++) acc[mi][nj][ci] = 0.f;

    for (int k0 = 0; k0 < NC; k0 += 32) {
#pragma unroll
        for (int i = 0; i < 4; i++) {
            int idx = tid + i * 256;
            int o = idx >> 3, c4 = (idx & 7) * 4;
            float4 w4 = *(const float4*)&W[(size_t)(oBase + o) * NC + k0 + c4];
            *(uint4*)&As[o][c4] = make_uint4(f2tf(w4.x), f2tf(w4.y), f2tf(w4.z), f2tf(w4.w));
        }
#pragma unroll
        for (int i = 0; i < 4; i++) {
            int idx = tid + i * 256;
            int c = idx >> 5, t4 = (idx & 31) * 4;
            float4 x4 = *(const float4*)&X[(size_t)(k0 + c) * NT + tBase + t4];
            Bs[t4 + 0][c] = f2tf(x4.x);
            Bs[t4 + 1][c] = f2tf(x4.y);
            Bs[t4 + 2][c] = f2tf(x4.z);
            Bs[t4 + 3][c] = f2tf(x4.w);
        }
        __syncthreads();
#pragma unroll
        for (int kk = 0; kk < 32; kk += 8) {
            uint32_t af[4][4], bf[4][2];
#pragma unroll
            for (int mi = 0; mi < 4; mi++) {
                int m0 = wm * 64 + mi * 16 + lr;
                af[mi][0] = As[m0][kk + lk];
                af[mi][1] = As[m0 + 8][kk + lk];
                af[mi][2] = As[m0][kk + lk + 4];
                af[mi][3] = As[m0 + 8][kk + lk + 4];
            }
#pragma unroll
            for (int nj = 0; nj < 4; nj++) {
                int n0 = wn * 32 + nj * 8 + lr;
                bf[nj][0] = Bs[n0][kk + lk];
                bf[nj][1] = Bs[n0][kk + lk + 4];
            }
#pragma unroll
            for (int mi = 0; mi < 4; mi++)
#pragma unroll
                for (int nj = 0; nj < 4; nj++) mma8(acc[mi][nj], af[mi], bf[nj]);
        }
        __syncthreads();
    }
#pragma unroll
    for (int mi = 0; mi < 4; mi++) {
        int r = oBase + wm * 64 + mi * 16 + lr;
#pragma unroll
        for (int nj = 0; nj < 4; nj++) {
            int cc = tBase + wn * 32 + nj * 8 + lk * 2;
            *(float2*)&out[(size_t)r * NT + cc] = make_float2(acc[mi][nj][0], acc[mi][nj][1]);
            *(float2*)&out[(size_t)(r + 8) * NT + cc] = make_float2(acc[mi][nj][2], acc[mi][nj][3]);
        }
    }
    if (which == 2) {
        __half* vh = g_vh + (size_t)b * NC * NT;
#pragma unroll
        for (int mi = 0; mi < 4; mi++) {
            int r = oBase + wm * 64 + mi * 16 + lr;
#pragma unroll
            for (int nj = 0; nj < 4; nj++) {
                int cc = tBase + wn * 32 + nj * 8 + lk * 2;
                *(__half2*)&vh[(size_t)r * NT + cc] =
                    __floats2half2_rn(acc[mi][nj][0], acc[mi][nj][1]);
                *(__half2*)&vh[(size_t)(r + 8) * NT + cc] =
                    __floats2half2_rn(acc[mi][nj][2], acc[mi][nj][3]);
            }
        }
    }
}

// ============ Kernel 2: QK^T. attn[q,T] = 0.125 * sum_d q[d,q] k[d,T] ============
__global__ __launch_bounds__(256) void qk_tf32() {
    int bh = blockIdx.z;
    int b = bh >> 3, h = bh & 7;
    const float* A = g_q + (size_t)(b * NC + h * NHD) * NT;
    const float* Bm = g_k + (size_t)(b * NC + h * NHD) * NT;
    float* out = g_attn + (size_t)bh * NT * NT;

    int qBase = blockIdx.y * 128;
    int tBase = blockIdx.x * 128;

    __shared__ uint32_t As[128][36];
    __shared__ uint32_t Bs[128][36];

    int tid = threadIdx.x, lane = tid & 31, wid = tid >> 5;
    int wm = wid >> 2, wn = wid & 3;
    int lr = lane >> 2, lk = lane & 3;

    float acc[4][4][4];
#pragma unroll
    for (int mi = 0; mi < 4; mi++)
#pragma unroll
        for (int nj = 0; nj < 4; nj++)
#pragma unroll
            for (int ci = 0; ci < 4; ci++) acc[mi][nj][ci] = 0.f;

    for (int k0 = 0; k0 < NHD; k0 += 32) {
#pragma unroll
        for (int i = 0; i < 4; i++) {
            int idx = tid + i * 256;
            int d = idx >> 5, m4 = (idx & 31) * 4;
            float4 a4 = *(const float4*)&A[(size_t)(k0 + d) * NT + qBase + m4];
            As[m4 + 0][d] = f2tf(a4.x);
            As[m4 + 1][d] = f2tf(a4.y);
            As[m4 + 2][d] = f2tf(a4.z);
            As[m4 + 3][d] = f2tf(a4.w);
            float4 b4 = *(const float4*)&Bm[(size_t)(k0 + d) * NT + tBase + m4];
            Bs[m4 + 0][d] = f2tf(b4.x);
            Bs[m4 + 1][d] = f2tf(b4.y);
            Bs[m4 + 2][d] = f2tf(b4.z);
            Bs[m4 + 3][d] = f2tf(b4.w);
        }
        __syncthreads();
#pragma unroll
        for (int kk = 0; kk < 32; kk += 8) {
            uint32_t af[4][4], bf[4][2];
#pragma unroll
            for (int mi = 0; mi < 4; mi++) {
                int m0 = wm * 64 + mi * 16 + lr;
                af[mi][0] = As[m0][kk + lk];
                af[mi][1] = As[m0 + 8][kk + lk];
                af[mi][2] = As[m0][kk + lk + 4];
                af[mi][3] = As[m0 + 8][kk + lk + 4];
            }
#pragma unroll
            for (int nj = 0; nj < 4; nj++) {
                int n0 = wn * 32 + nj * 8 + lr;
                bf[nj][0] = Bs[n0][kk + lk];
                bf[nj][1] = Bs[n0][kk + lk + 4];
            }
#pragma unroll
            for (int mi = 0; mi < 4; mi++)
#pragma unroll
                for (int nj = 0; nj < 4; nj++) mma8(acc[mi][nj], af[mi], bf[nj]);
        }
        __syncthreads();
    }
#pragma unroll
    for (int mi = 0; mi < 4; mi++) {
        int r = qBase + wm * 64 + mi * 16 + lr;
#pragma unroll
        for (int nj = 0; nj < 4; nj++) {
            int cc = tBase + wn * 32 + nj * 8 + lk * 2;
            *(float2*)&out[(size_t)r * NT + cc] =
                make_float2(acc[mi][nj][0] * 0.125f, acc[mi][nj][1] * 0.125f);
            *(float2*)&out[(size_t)(r + 8) * NT + cc] =
                make_float2(acc[mi][nj][2] * 0.125f, acc[mi][nj][3] * 0.125f);
        }
    }
}

// ============ Kernel 3: head-mix + softmax (registers) -> fp16 probs ============
// Block = (q, b). Thread t owns T positions 4t..4t+3 for all 8 mixed heads.
__global__ __launch_bounds__(256) void mixsm_kernel(const float* __restrict__ w_head) {
    int q = blockIdx.x, b = blockIdx.y;
    int t = threadIdx.x;
    int lane = t & 31, wid = t >> 5;

    __shared__ float wh[64];
    __shared__ float red[8][36];
    __shared__ float red2[8][36];
    __shared__ float fin[8], fin2[8];

    if (t < 64) wh[t] = w_head[t];
    __syncthreads();

    float raw[8][4];
#pragma unroll
    for (int h = 0; h < 8; h++) {
        float4 r4 = *(const float4*)&g_attn[(((size_t)(b * 8 + h)) * NT + q) * NT + t * 4];
        raw[h][0] = r4.x; raw[h][1] = r4.y; raw[h][2] = r4.z; raw[h][3] = r4.w;
    }

    float m[8][4];
#pragma unroll
    for (int g = 0; g < 8; g++) {
#pragma unroll
        for (int j = 0; j < 4; j++) {
            float acc = 0.f;
#pragma unroll
            for (int h = 0; h < 8; h++) acc += wh[g * 8 + h] * raw[h][j];
            m[g][j] = acc;
        }
    }

    // block max per g: 3-step warp partial -> 32-wide second stage
#pragma unroll
    for (int g = 0; g < 8; g++) {
        float v = fmaxf(fmaxf(m[g][0], m[g][1]), fmaxf(m[g][2], m[g][3]));
        v = fmaxf(v, __shfl_xor_sync(0xffffffffu, v, 16));
        v = fmaxf(v, __shfl_xor_sync(0xffffffffu, v, 8));
        v = fmaxf(v, __shfl_xor_sync(0xffffffffu, v, 4));
        if (lane < 4) red[g][wid * 4 + lane] = v;
    }
    __syncthreads();
    {
        int g = t >> 5;
        float v = red[g][lane];
        v = fmaxf(v, __shfl_xor_sync(0xffffffffu, v, 16));
        v = fmaxf(v, __shfl_xor_sync(0xffffffffu, v, 8));
        v = fmaxf(v, __shfl_xor_sync(0xffffffffu, v, 4));
        v = fmaxf(v, __shfl_xor_sync(0xffffffffu, v, 2));
        v = fmaxf(v, __shfl_xor_sync(0xffffffffu, v, 1));
        if (lane == 0) fin[g] = v;
    }
    __syncthreads();

    float s[8], s2[8];
#pragma unroll
    for (int g = 0; g < 8; g++) {
        float mx = fin[g];
        float e0 = __expf(m[g][0] - mx);
        float e1 = __expf(m[g][1] - mx);
        float e2 = __expf(m[g][2] - mx);
        float e3 = __expf(m[g][3] - mx);
        m[g][0] = e0; m[g][1] = e1; m[g][2] = e2; m[g][3] = e3;
        s[g] = (e0 + e1) + (e2 + e3);
        s2[g] = (e0 * e0 + e1 * e1) + (e2 * e2 + e3 * e3);
    }
    __syncthreads();

#pragma unroll
    for (int g = 0; g < 8; g++) {
        float v = s[g], w2 = s2[g];
        v += __shfl_xor_sync(0xffffffffu, v, 16);
        w2 += __shfl_xor_sync(0xffffffffu, w2, 16);
        v += __shfl_xor_sync(0xffffffffu, v, 8);
        w2 += __shfl_xor_sync(0xffffffffu, w2, 8);
        v += __shfl_xor_sync(0xffffffffu, v, 4);
        w2 += __shfl_xor_sync(0xffffffffu, w2, 4);
        if (lane < 4) { red[g][wid * 4 + lane] = v; red2[g][wid * 4 + lane] = w2; }
    }
    __syncthreads();
    {
        int g = t >> 5;
        float v = red[g][lane], w2 = red2[g][lane];
        v += __shfl_xor_sync(0xffffffffu, v, 16);
        w2 += __shfl_xor_sync(0xffffffffu, w2, 16);
        v += __shfl_xor_sync(0xffffffffu, v, 8);
        w2 += __shfl_xor_sync(0xffffffffu, w2, 8);
        v += __shfl_xor_sync(0xffffffffu, v, 4);
        w2 += __shfl_xor_sync(0xffffffffu, w2, 4);
        v += __shfl_xor_sync(0xffffffffu, v, 2);
        w2 += __shfl_xor_sync(0xffffffffu, w2, 2);
        v += __shfl_xor_sync(0xffffffffu, v, 1);
        w2 += __shfl_xor_sync(0xffffffffu, w2, 1);
        if (lane == 0) { fin[g] = v; fin2[g] = w2; }
    }
    __syncthreads();

#pragma unroll
    for (int g = 0; g < 8; g++) {
        float inv = 1.f / fin[g];
        __half2 h0 = __floats2half2_rn(m[g][0] * inv, m[g][1] * inv);
        __half2 h1 = __floats2half2_rn(m[g][2] * inv, m[g][3] * inv);
        uint2 u;
        u.x = *(uint32_t*)&h0;
        u.y = *(uint32_t*)&h1;
        *(uint2*)&g_ph[(((size_t)(b * 8 + g)) * NT + q) * NT + t * 4] = u;
    }
    if (t < 8) {
        float sv = fin[t];
        g_rowsq[(b * 8 + t) * NT + q] = fin2[t] / (sv * sv);
    }
}

// ============ Kernel 4: vsum ============
__global__ __launch_bounds__(256) void vsum_kernel() {
    __shared__ float sbuf[8];
    int row = blockIdx.x;
    float4 p = *(const float4*)&g_v[(size_t)row * NT + threadIdx.x * 4];
    float s = p.x + p.y + p.z + p.w;
    int lane = threadIdx.x & 31, w = threadIdx.x >> 5;
#pragma unroll
    for (int o = 16; o > 0; o >>= 1) s += __shfl_xor_sync(0xffffffffu, s, o);
    if (lane == 0) sbuf[w] = s;
    __syncthreads();
    if (threadIdx.x == 0) {
        float t = 0.f;
        for (int i = 0; i < 8; i++) t += sbuf[i];
        g_vsum[row] = t;
    }
}

// ============ Kernel 5: finalize InstanceNorm params ============
__global__ __launch_bounds__(256) void finalize_kernel(const float* __restrict__ gamma,
                                                       const float* __restrict__ beta) {
    __shared__ float sbuf[8];
    int grp = blockIdx.x;
    float s = 0.f;
    for (int i = threadIdx.x; i < NT; i += 256) s += g_rowsq[grp * NT + i];
    int lane = threadIdx.x & 31, w = threadIdx.x >> 5;
#pragma unroll
    for (int o = 16; o > 0; o >>= 1) s += __shfl_xor_sync(0xffffffffu, s, o);
    if (lane == 0) sbuf[w] = s;
    __syncthreads();
    if (threadIdx.x == 0) {
        float sumsq = 0.f;
        for (int i = 0; i < 8; i++) sumsq += sbuf[i];
        const float invN = 1.f / (1024.f * 1024.f);
        float mean = 1.f / 1024.f;
        float var = sumsq * invN - mean * mean;
        int h = grp & 7;
        float alpha = gamma[h] * rsqrtf(var + EPS_IN);
        g_alpha[grp] = alpha;
        g_betac[grp] = beta[h] - alpha * mean;
    }
}

// ============ Kernel 6: AV (fp16 mma) + folded InstanceNorm ============
// out[q,d] = alpha * sum_T p[q,T] v[d,T] + betac * vsum[d]
__global__ __launch_bounds__(256) void av_fp16() {
    int bh = blockIdx.y;
    int b = bh >> 3, h = bh & 7;
    const __half* P = g_ph + (size_t)bh * NT * NT;                 // [q][T]
    const __half* V = g_vh + (size_t)(b * NC + h * NHD) * NT;      // [d][T]
    float* out = g_out + (size_t)bh * NT * NHD;
    int qBase = blockIdx.x * 128;

    __shared__ uint32_t Ps[128][20];   // half2: [q][T/2]
    __shared__ uint32_t Vs[64][20];    // half2: [d][T/2]

    int tid = threadIdx.x, lane = tid & 31, wid = tid >> 5;
    int wm = wid >> 1, wn = wid & 1;
    int lr = lane >> 2, lk = lane & 3;

    float acc[2][4][4];
#pragma unroll
    for (int mi = 0; mi < 2; mi++)
#pragma unroll
        for (int nj = 0; nj < 4; nj++)
#pragma unroll
            for (int ci = 0; ci < 4; ci++) acc[mi][nj][ci] = 0.f;

    for (int k0 = 0; k0 < NT; k0 += 32) {
#pragma unroll
        for (int pass = 0; pass < 2; pass++) {
            int idx = tid + pass * 256;
            int row = idx >> 2, seg = idx & 3;
            uint4 pv = *(const uint4*)&P[(size_t)(qBase + row) * NT + k0 + seg * 8];
            *(uint4*)&Ps[row][seg * 4] = pv;
        }
        {
            int row = tid >> 2, seg = tid & 3;
            uint4 vv = *(const uint4*)&V[(size_t)row * NT + k0 + seg * 8];
            *(uint4*)&Vs[row][seg * 4] = vv;
        }
        __syncthreads();
#pragma unroll
        for (int ci = 0; ci < 2; ci++) {
            int kc = ci * 8;
            uint32_t af[2][4], bf[4][2];
#pragma unroll
            for (int mi = 0; mi < 2; mi++) {
                int m0 = wm * 32 + mi * 16 + lr;
                af[mi][0] = Ps[m0][kc + lk];
                af[mi][1] = Ps[m0 + 8][kc + lk];
                af[mi][2] = Ps[m0][kc + lk + 4];
                af[mi][3] = Ps[m0 + 8][kc + lk + 4];
            }
#pragma unroll
            for (int nj = 0; nj < 4; nj++) {
                int n0 = wn * 32 + nj * 8 + lr;
                bf[nj][0] = Vs[n0][kc + lk];
                bf[nj][1] = Vs[n0][kc + lk + 4];
            }
#pragma unroll
            for (int mi = 0; mi < 2; mi++)
#pragma unroll
                for (int nj = 0; nj < 4; nj++) mma16h(acc[mi][nj], af[mi], bf[nj]);
        }
        __syncthreads();
    }

    float alpha = g_alpha[bh], bc = g_betac[bh];
#pragma unroll
    for (int mi = 0; mi < 2; mi++) {
        int r = qBase + wm * 32 + mi * 16 + lr;
#pragma unroll
        for (int nj = 0; nj < 4; nj++) {
            int d0 = wn * 32 + nj * 8 + lk * 2;
            float vs0 = g_vsum[bh * NHD + d0], vs1 = g_vsum[bh * NHD + d0 + 1];
            *(float2*)&out[(size_t)r * NHD + d0] =
                make_float2(alpha * acc[mi][nj][0] + bc * vs0,
                            alpha * acc[mi][nj][1] + bc * vs1);
            *(float2*)&out[(size_t)(r + 8) * NHD + d0] =
                make_float2(alpha * acc[mi][nj][2] + bc * vs0,
                            alpha * acc[mi][nj][3] + bc * vs1);
        }
    }
}

// ============ Kernel 7: projection ============
__global__ __launch_bounds__(256) void proj_tf32(const float* __restrict__ w_proj,
                                                 const float* __restrict__ b_proj,
                                                 float* __restrict__ outF) {
    int b = blockIdx.z;
    int coBase = blockIdx.y * 128;
    int tBase = blockIdx.x * 128;
    const float* mid = g_out + (size_t)b * NT * NC;

    __shared__ uint32_t As[128][36];
    __shared__ uint32_t Bs[128][36];

    int tid = threadIdx.x, lane = tid & 31, wid = tid >> 5;
    int wm = wid >> 2, wn = wid & 3;
    int lr = lane >> 2, lk = lane & 3;

    float acc[4][4][4];
#pragma unroll
    for (int mi = 0; mi < 4; mi++)
#pragma unroll
        for (int nj = 0; nj < 4; nj++)
#pragma unroll
            for (int ci = 0; ci < 4; ci++) acc[mi][nj][ci] = 0.f;

    for (int k0 = 0; k0 < NC; k0 += 32) {
#pragma unroll
        for (int i = 0; i < 4; i++) {
            int idx = tid + i * 256;
            int r = idx >> 3, c4 = (idx & 7) * 4;
            float4 w4 = *(const float4*)&w_proj[(size_t)(coBase + r) * NC + k0 + c4];
            *(uint4*)&As[r][c4] = make_uint4(f2tf(w4.x), f2tf(w4.y), f2tf(w4.z), f2tf(w4.w));
            float4 m4 = *(const float4*)&mid[(size_t)(tBase + r) * NC + k0 + c4];
            *(uint4*)&Bs[r][c4] = make_uint4(f2tf(m4.x), f2tf(m4.y), f2tf(m4.z), f2tf(m4.w));
        }
        __syncthreads();
#pragma unroll
        for (int kk = 0; kk < 32; kk += 8) {
            uint32_t af[4][4], bf[4][2];
#pragma unroll
            for (int mi = 0; mi < 4; mi++) {
                int m0 = wm * 64 + mi * 16 + lr;
                af[mi][0] = As[m0][kk + lk];
                af[mi][1] = As[m0 + 8][kk + lk];
                af[mi][2] = As[m0][kk + lk + 4];
                af[mi][3] = As[m0 + 8][kk + lk + 4];
            }
#pragma unroll
            for (int nj = 0; nj < 4; nj++) {
                int n0 = wn * 32 + nj * 8 + lr;
                bf[nj][0] = Bs[n0][kk + lk];
                bf[nj][1] = Bs[n0][kk + lk + 4];
            }
#pragma unroll
            for (int mi = 0; mi < 4; mi++)
#pragma unroll
                for (int nj = 0; nj < 4; nj++) mma8(acc[mi][nj], af[mi], bf[nj]);
        }
        __syncthreads();
    }
#pragma unroll
    for (int mi = 0; mi < 4; mi++) {
        int co = coBase + wm * 64 + mi * 16 + lr;
        float bias0 = b_proj[co], bias1 = b_proj[co + 8];
        float* op0 = outF + (size_t)b * NC * NT + (size_t)co * NT;
        float* op1 = op0 + (size_t)8 * NT;
#pragma unroll
        for (int nj = 0; nj < 4; nj++) {
            int cc = tBase + wn * 32 + nj * 8 + lk * 2;
            *(float2*)&op0[cc] = make_float2(acc[mi][nj][0] + bias0, acc[mi][nj][1] + bias0);
            *(float2*)&op1[cc] = make_float2(acc[mi][nj][2] + bias1, acc[mi][nj][3] + bias1);
        }
    }
}

// ---------------- launch ----------------
extern "C" void kernel_launch(void* const* d_in, const int* in_sizes, int n_in,
                              void* d_out, int out_size) {
    (void)in_sizes; (void)n_in; (void)out_size;
    const float* x        = (const float*)d_in[0];
    const float* w_q      = (const float*)d_in[1];
    const float* w_k      = (const float*)d_in[2];
    const float* w_v      = (const float*)d_in[3];
    const float* w_head   = (const float*)d_in[4];
    const float* in_gamma = (const float*)d_in[5];
    const float* in_beta  = (const float*)d_in[6];
    const float* w_proj   = (const float*)d_in[7];
    const float* b_proj   = (const float*)d_in[8];
    float* outF = (float*)d_out;

    qkv_tf32<<<dim3(8, 4, 12), 256>>>(x, w_q, w_k, w_v);
    qk_tf32<<<dim3(8, 8, 32), 256>>>();
    mixsm_kernel<<<dim3(1024, 4), 256>>>(w_head);
    vsum_kernel<<<2048, 256>>>();
    finalize_kernel<<<32, 256>>>(in_gamma, in_beta);
    av_fp16<<<dim3(8, 32), 256>>>();
    proj_tf32<<<dim3(8, 4, 4), 256>>>(w_proj, b_proj, outF);
}

// round 6
// speedup vs baseline: 1.7287x; 1.7287x over previous
#include <cuda_runtime.h>
#include <cuda_fp16.h>
#include <math.h>
#include <stdint.h>

#define NB 4
#define NC 512
#define NT 1024
#define NHEADS 8
#define NHD 64
#define EPS_IN 1e-5f

// ---------------- device scratch ----------------
__device__ __half g_w16[4 * NC * NC];                      // wq,wk,wv,wproj fp16
__device__ __half g_xT[NB * NT * NC];                      // x transposed [b][t][c]
__device__ __half g_qT[NB * NT * NC];                      // q transposed [b][t][c]
__device__ __half g_kT[NB * NT * NC];                      // k transposed [b][t][c]
__device__ __half g_vh[NB * NC * NT];                      // v [b][c][t]
__device__ float g_attn[(size_t)NB * NHEADS * NT * NT];    // raw logits fp32 134MB
__device__ __half g_ph[(size_t)NB * NHEADS * NT * NT];     // softmax probs fp16 67MB
__device__ __half g_outh[NB * NHEADS * NT * NHD];          // mid [b][t][c] fp16
__device__ float g_vsum[NB * NC];
__device__ float g_rowsq[NB * NHEADS * NT];
__device__ float g_alpha[32];
__device__ float g_betac[32];

__device__ __forceinline__ void mma16h(float* c, const uint32_t* a, const uint32_t* b) {
    asm volatile("mma.sync.aligned.m16n8k16.row.col.f32.f16.f16.f32 "
        "{%0,%1,%2,%3}, {%4,%5,%6,%7}, {%8,%9}, {%0,%1,%2,%3};\n"
        : "+f"(c[0]), "+f"(c[1]), "+f"(c[2]), "+f"(c[3])
        : "r"(a[0]), "r"(a[1]), "r"(a[2]), "r"(a[3]), "r"(b[0]), "r"(b[1]));
}

// ============ prep: weights -> fp16 ============
__global__ __launch_bounds__(256) void prep_w(const float* __restrict__ wq,
                                              const float* __restrict__ wk,
                                              const float* __restrict__ wv,
                                              const float* __restrict__ wp) {
    int idx = blockIdx.x * 256 + threadIdx.x;   // 4*262144 total
    int which = idx >> 18, off = idx & 262143;
    const float* s = (which == 0) ? wq : (which == 1) ? wk : (which == 2) ? wv : wp;
    g_w16[idx] = __float2half(s[off]);
}

// ============ prep: xT[b][t][c] fp16 ============
__global__ __launch_bounds__(256) void prep_x(const float* __restrict__ x) {
    __shared__ float tile[32][33];
    int tx = threadIdx.x, ty = threadIdx.y;   // (32,8)
    int tBase = blockIdx.x * 32, cBase = blockIdx.y * 32, b = blockIdx.z;
    const float* X = x + (size_t)b * NC * NT;
#pragma unroll
    for (int p = 0; p < 4; p++)
        tile[ty + 8 * p][tx] = X[(size_t)(cBase + ty + 8 * p) * NT + tBase + tx];
    __syncthreads();
    __half* dst = g_xT + (size_t)b * NT * NC;
#pragma unroll
    for (int p = 0; p < 4; p++)
        dst[(size_t)(tBase + ty + 8 * p) * NC + cBase + tx] = __float2half(tile[tx][ty + 8 * p]);
}

// ============ Kernel 1: QKV fp16. out[o,t] = sum_c W[o,c] x[c,t] ============
// Block 128x128, BK=32, warps 2x4. q,k written transposed via smem stage; v direct.
__global__ __launch_bounds__(256) void qkv_f16() {
    int z = blockIdx.z;
    int b = z / 3, which = z - b * 3;
    const __half* W = g_w16 + (size_t)which * NC * NC;
    const __half* X = g_xT + (size_t)b * NT * NC;

    int oBase = blockIdx.y * 128;
    int tBase = blockIdx.x * 128;

    __shared__ union {
        struct { uint32_t A[128][20]; uint32_t B[128][20]; } ab;
        unsigned short st[128][136];
    } smu;

    int tid = threadIdx.x, lane = tid & 31, wid = tid >> 5;
    int wm = wid >> 2, wn = wid & 3;
    int lr = lane >> 2, lk = lane & 3;

    float acc[4][4][4];
#pragma unroll
    for (int mi = 0; mi < 4; mi++)
#pragma unroll
        for (int nj = 0; nj < 4; nj++)
#pragma unroll
            for (int ci = 0; ci < 4; ci++) acc[mi][nj][ci] = 0.f;

    for (int k0 = 0; k0 < NC; k0 += 32) {
#pragma unroll
        for (int i = 0; i < 2; i++) {
            int idx = tid + i * 256;
            int row = idx >> 2, uu = idx & 3;
            *(uint4*)&smu.ab.A[row][uu * 4] =
                *(const uint4*)&W[(size_t)(oBase + row) * NC + k0 + uu * 8];
            *(uint4*)&smu.ab.B[row][uu * 4] =
                *(const uint4*)&X[(size_t)(tBase + row) * NC + k0 + uu * 8];
        }
        __syncthreads();
#pragma unroll
        for (int ci = 0; ci < 2; ci++) {
            int kc = ci * 8;
            uint32_t af[4][4], bf[4][2];
#pragma unroll
            for (int mi = 0; mi < 4; mi++) {
                int m0 = wm * 64 + mi * 16 + lr;
                af[mi][0] = smu.ab.A[m0][kc + lk];
                af[mi][1] = smu.ab.A[m0 + 8][kc + lk];
                af[mi][2] = smu.ab.A[m0][kc + lk + 4];
                af[mi][3] = smu.ab.A[m0 + 8][kc + lk + 4];
            }
#pragma unroll
            for (int nj = 0; nj < 4; nj++) {
                int n0 = wn * 32 + nj * 8 + lr;
                bf[nj][0] = smu.ab.B[n0][kc + lk];
                bf[nj][1] = smu.ab.B[n0][kc + lk + 4];
            }
#pragma unroll
            for (int mi = 0; mi < 4; mi++)
#pragma unroll
                for (int nj = 0; nj < 4; nj++) mma16h(acc[mi][nj], af[mi], bf[nj]);
        }
        __syncthreads();
    }

    if (which == 2) {
        // v: write fp16 [c][t] directly
        __half* vh = g_vh + (size_t)b * NC * NT;
#pragma unroll
        for (int mi = 0; mi < 4; mi++) {
            int r = oBase + wm * 64 + mi * 16 + lr;
#pragma unroll
            for (int nj = 0; nj < 4; nj++) {
                int cc = tBase + wn * 32 + nj * 8 + lk * 2;
                *(__half2*)&vh[(size_t)r * NT + cc] =
                    __floats2half2_rn(acc[mi][nj][0], acc[mi][nj][1]);
                *(__half2*)&vh[(size_t)(r + 8) * NT + cc] =
                    __floats2half2_rn(acc[mi][nj][2], acc[mi][nj][3]);
            }
        }
    } else {
        // q/k: transpose-stage in smem, then write [t][c] fp16 coalesced
        __half* dst = ((which == 0) ? g_qT : g_kT) + (size_t)b * NT * NC;
#pragma unroll
        for (int mi = 0; mi < 4; mi++) {
            int r = wm * 64 + mi * 16 + lr;
#pragma unroll
            for (int nj = 0; nj < 4; nj++) {
                int cc = wn * 32 + nj * 8 + lk * 2;
                smu.st[cc][r]         = __half_as_ushort(__float2half(acc[mi][nj][0]));
                smu.st[cc + 1][r]     = __half_as_ushort(__float2half(acc[mi][nj][1]));
                smu.st[cc][r + 8]     = __half_as_ushort(__float2half(acc[mi][nj][2]));
                smu.st[cc + 1][r + 8] = __half_as_ushort(__float2half(acc[mi][nj][3]));
            }
        }
        __syncthreads();
        int row = tid >> 1, ub = (tid & 1) * 8;
#pragma unroll
        for (int j = 0; j < 8; j++) {
            *(uint4*)&dst[(size_t)(tBase + row) * NC + oBase + (ub + j) * 8] =
                *(const uint4*)&smu.st[row][(ub + j) * 8];
        }
    }
}

// ============ Kernel 2: QK^T fp16. attn[q,T] = 0.125 * sum_d q[q,d] k[T,d] ============
// K=64, single stage. Block 128x128, warps 2x4.
__global__ __launch_bounds__(256) void qk_f16() {
    int bh = blockIdx.z;
    int b = bh >> 3, h = bh & 7;
    const __half* Aq = g_qT + (size_t)b * NT * NC;
    const __half* Bk = g_kT + (size_t)b * NT * NC;
    float* out = g_attn + (size_t)bh * NT * NT;

    int qBase = blockIdx.y * 128;
    int tBase = blockIdx.x * 128;

    __shared__ uint32_t As[128][36];   // [q][d/2], KU=32 pad 36
    __shared__ uint32_t Bs[128][36];   // [T][d/2]

    int tid = threadIdx.x, lane = tid & 31, wid = tid >> 5;
    int wm = wid >> 2, wn = wid & 3;
    int lr = lane >> 2, lk = lane & 3;

#pragma unroll
    for (int i = 0; i < 4; i++) {
        int idx = tid + i * 256;
        int row = idx >> 3, uu = idx & 7;
        *(uint4*)&As[row][uu * 4] =
            *(const uint4*)&Aq[(size_t)(qBase + row) * NC + h * 64 + uu * 8];
        *(uint4*)&Bs[row][uu * 4] =
            *(const uint4*)&Bk[(size_t)(tBase + row) * NC + h * 64 + uu * 8];
    }
    __syncthreads();

    float acc[4][4][4];
#pragma unroll
    for (int mi = 0; mi < 4; mi++)
#pragma unroll
        for (int nj = 0; nj < 4; nj++)
#pragma unroll
            for (int ci = 0; ci < 4; ci++) acc[mi][nj][ci] = 0.f;

#pragma unroll
    for (int ci = 0; ci < 4; ci++) {
        int kc = ci * 8;
        uint32_t af[4][4], bf[4][2];
#pragma unroll
        for (int mi = 0; mi < 4; mi++) {
            int m0 = wm * 64 + mi * 16 + lr;
            af[mi][0] = As[m0][kc + lk];
            af[mi][1] = As[m0 + 8][kc + lk];
            af[mi][2] = As[m0][kc + lk + 4];
            af[mi][3] = As[m0 + 8][kc + lk + 4];
        }
#pragma unroll
        for (int nj = 0; nj < 4; nj++) {
            int n0 = wn * 32 + nj * 8 + lr;
            bf[nj][0] = Bs[n0][kc + lk];
            bf[nj][1] = Bs[n0][kc + lk + 4];
        }
#pragma unroll
        for (int mi = 0; mi < 4; mi++)
#pragma unroll
            for (int nj = 0; nj < 4; nj++) mma16h(acc[mi][nj], af[mi], bf[nj]);
    }

#pragma unroll
    for (int mi = 0; mi < 4; mi++) {
        int r = qBase + wm * 64 + mi * 16 + lr;
#pragma unroll
        for (int nj = 0; nj < 4; nj++) {
            int cc = tBase + wn * 32 + nj * 8 + lk * 2;
            *(float2*)&out[(size_t)r * NT + cc] =
                make_float2(acc[mi][nj][0] * 0.125f, acc[mi][nj][1] * 0.125f);
            *(float2*)&out[(size_t)(r + 8) * NT + cc] =
                make_float2(acc[mi][nj][2] * 0.125f, acc[mi][nj][3] * 0.125f);
        }
    }
}

// ============ Kernel 3: head-mix + softmax -> fp16 probs ============
__global__ __launch_bounds__(256) void mixsm_kernel(const float* __restrict__ w_head) {
    int q = blockIdx.x, b = blockIdx.y;
    int t = threadIdx.x;
    int lane = t & 31, wid = t >> 5;

    __shared__ float wh[64];
    __shared__ float red[8][36];
    __shared__ float red2[8][36];
    __shared__ float fin[8], fin2[8];

    if (t < 64) wh[t] = w_head[t];
    __syncthreads();

    float raw[8][4];
#pragma unroll
    for (int h = 0; h < 8; h++) {
        float4 r4 = *(const float4*)&g_attn[(((size_t)(b * 8 + h)) * NT + q) * NT + t * 4];
        raw[h][0] = r4.x; raw[h][1] = r4.y; raw[h][2] = r4.z; raw[h][3] = r4.w;
    }

    float m[8][4];
#pragma unroll
    for (int g = 0; g < 8; g++) {
#pragma unroll
        for (int j = 0; j < 4; j++) {
            float a = 0.f;
#pragma unroll
            for (int h = 0; h < 8; h++) a += wh[g * 8 + h] * raw[h][j];
            m[g][j] = a;
        }
    }

#pragma unroll
    for (int g = 0; g < 8; g++) {
        float v = fmaxf(fmaxf(m[g][0], m[g][1]), fmaxf(m[g][2], m[g][3]));
        v = fmaxf(v, __shfl_xor_sync(0xffffffffu, v, 16));
        v = fmaxf(v, __shfl_xor_sync(0xffffffffu, v, 8));
        v = fmaxf(v, __shfl_xor_sync(0xffffffffu, v, 4));
        if (lane < 4) red[g][wid * 4 + lane] = v;
    }
    __syncthreads();
    {
        int g = t >> 5;
        float v = red[g][lane];
        v = fmaxf(v, __shfl_xor_sync(0xffffffffu, v, 16));
        v = fmaxf(v, __shfl_xor_sync(0xffffffffu, v, 8));
        v = fmaxf(v, __shfl_xor_sync(0xffffffffu, v, 4));
        v = fmaxf(v, __shfl_xor_sync(0xffffffffu, v, 2));
        v = fmaxf(v, __shfl_xor_sync(0xffffffffu, v, 1));
        if (lane == 0) fin[g] = v;
    }
    __syncthreads();

    float s[8], s2[8];
#pragma unroll
    for (int g = 0; g < 8; g++) {
        float mx = fin[g];
        float e0 = __expf(m[g][0] - mx);
        float e1 = __expf(m[g][1] - mx);
        float e2 = __expf(m[g][2] - mx);
        float e3 = __expf(m[g][3] - mx);
        m[g][0] = e0; m[g][1] = e1; m[g][2] = e2; m[g][3] = e3;
        s[g] = (e0 + e1) + (e2 + e3);
        s2[g] = (e0 * e0 + e1 * e1) + (e2 * e2 + e3 * e3);
    }
    __syncthreads();

#pragma unroll
    for (int g = 0; g < 8; g++) {
        float v = s[g], w2 = s2[g];
        v += __shfl_xor_sync(0xffffffffu, v, 16);
        w2 += __shfl_xor_sync(0xffffffffu, w2, 16);
        v += __shfl_xor_sync(0xffffffffu, v, 8);
        w2 += __shfl_xor_sync(0xffffffffu, w2, 8);
        v += __shfl_xor_sync(0xffffffffu, v, 4);
        w2 += __shfl_xor_sync(0xffffffffu, w2, 4);
        if (lane < 4) { red[g][wid * 4 + lane] = v; red2[g][wid * 4 + lane] = w2; }
    }
    __syncthreads();
    {
        int g = t >> 5;
        float v = red[g][lane], w2 = red2[g][lane];
        v += __shfl_xor_sync(0xffffffffu, v, 16);
        w2 += __shfl_xor_sync(0xffffffffu, w2, 16);
        v += __shfl_xor_sync(0xffffffffu, v, 8);
        w2 += __shfl_xor_sync(0xffffffffu, w2, 8);
        v += __shfl_xor_sync(0xffffffffu, v, 4);
        w2 += __shfl_xor_sync(0xffffffffu, w2, 4);
        v += __shfl_xor_sync(0xffffffffu, v, 2);
        w2 += __shfl_xor_sync(0xffffffffu, w2, 2);
        v += __shfl_xor_sync(0xffffffffu, v, 1);
        w2 += __shfl_xor_sync(0xffffffffu, w2, 1);
        if (lane == 0) { fin[g] = v; fin2[g] = w2; }
    }
    __syncthreads();

#pragma unroll
    for (int g = 0; g < 8; g++) {
        float inv = 1.f / fin[g];
        __half2 h0 = __floats2half2_rn(m[g][0] * inv, m[g][1] * inv);
        __half2 h1 = __floats2half2_rn(m[g][2] * inv, m[g][3] * inv);
        uint2 u;
        u.x = *(uint32_t*)&h0;
        u.y = *(uint32_t*)&h1;
        *(uint2*)&g_ph[(((size_t)(b * 8 + g)) * NT + q) * NT + t * 4] = u;
    }
    if (t < 8) {
        float sv = fin[t];
        g_rowsq[(b * 8 + t) * NT + q] = fin2[t] / (sv * sv);
    }
}

// ============ Kernel 4: vsum from fp16 v ============
__global__ __launch_bounds__(256) void vsum_f16() {
    __shared__ float sbuf[8];
    int row = blockIdx.x;
    const __half2* p = (const __half2*)(g_vh + (size_t)row * NT) + threadIdx.x * 2;
    float2 a = __half22float2(p[0]);
    float2 bb = __half22float2(p[1]);
    float s = (a.x + a.y) + (bb.x + bb.y);
    int lane = threadIdx.x & 31, w = threadIdx.x >> 5;
#pragma unroll
    for (int o = 16; o > 0; o >>= 1) s += __shfl_xor_sync(0xffffffffu, s, o);
    if (lane == 0) sbuf[w] = s;
    __syncthreads();
    if (threadIdx.x == 0) {
        float tt = 0.f;
        for (int i = 0; i < 8; i++) tt += sbuf[i];
        g_vsum[row] = tt;
    }
}

// ============ Kernel 5: finalize InstanceNorm params ============
__global__ __launch_bounds__(256) void finalize_kernel(const float* __restrict__ gamma,
                                                       const float* __restrict__ beta) {
    __shared__ float sbuf[8];
    int grp = blockIdx.x;
    float s = 0.f;
    for (int i = threadIdx.x; i < NT; i += 256) s += g_rowsq[grp * NT + i];
    int lane = threadIdx.x & 31, w = threadIdx.x >> 5;
#pragma unroll
    for (int o = 16; o > 0; o >>= 1) s += __shfl_xor_sync(0xffffffffu, s, o);
    if (lane == 0) sbuf[w] = s;
    __syncthreads();
    if (threadIdx.x == 0) {
        float sumsq = 0.f;
        for (int i = 0; i < 8; i++) sumsq += sbuf[i];
        const float invN = 1.f / (1024.f * 1024.f);
        float mean = 1.f / 1024.f;
        float var = sumsq * invN - mean * mean;
        int h = grp & 7;
        float alpha = gamma[h] * rsqrtf(var + EPS_IN);
        g_alpha[grp] = alpha;
        g_betac[grp] = beta[h] - alpha * mean;
    }
}

// ============ Kernel 6: AV fp16 + folded InstanceNorm -> fp16 mid ============
__global__ __launch_bounds__(256) void av_fp16() {
    int bh = blockIdx.y;
    int b = bh >> 3, h = bh & 7;
    const __half* P = g_ph + (size_t)bh * NT * NT;
    const __half* V = g_vh + (size_t)(b * NC + h * NHD) * NT;
    __half* outh = g_outh + (size_t)bh * NT * NHD;
    int qBase = blockIdx.x * 128;

    __shared__ uint32_t Ps[128][20];
    __shared__ uint32_t Vs[64][20];

    int tid = threadIdx.x, lane = tid & 31, wid = tid >> 5;
    int wm = wid >> 1, wn = wid & 1;
    int lr = lane >> 2, lk = lane & 3;

    float acc[2][4][4];
#pragma unroll
    for (int mi = 0; mi < 2; mi++)
#pragma unroll
        for (int nj = 0; nj < 4; nj++)
#pragma unroll
            for (int ci = 0; ci < 4; ci++) acc[mi][nj][ci] = 0.f;

    for (int k0 = 0; k0 < NT; k0 += 32) {
#pragma unroll
        for (int pass = 0; pass < 2; pass++) {
            int idx = tid + pass * 256;
            int row = idx >> 2, seg = idx & 3;
            *(uint4*)&Ps[row][seg * 4] =
                *(const uint4*)&P[(size_t)(qBase + row) * NT + k0 + seg * 8];
        }
        {
            int row = tid >> 2, seg = tid & 3;
            *(uint4*)&Vs[row][seg * 4] =
                *(const uint4*)&V[(size_t)row * NT + k0 + seg * 8];
        }
        __syncthreads();
#pragma unroll
        for (int ci = 0; ci < 2; ci++) {
            int kc = ci * 8;
            uint32_t af[2][4], bf[4][2];
#pragma unroll
            for (int mi = 0; mi < 2; mi++) {
                int m0 = wm * 32 + mi * 16 + lr;
                af[mi][0] = Ps[m0][kc + lk];
                af[mi][1] = Ps[m0 + 8][kc + lk];
                af[mi][2] = Ps[m0][kc + lk + 4];
                af[mi][3] = Ps[m0 + 8][kc + lk + 4];
            }
#pragma unroll
            for (int nj = 0; nj < 4; nj++) {
                int n0 = wn * 32 + nj * 8 + lr;
                bf[nj][0] = Vs[n0][kc + lk];
                bf[nj][1] = Vs[n0][kc + lk + 4];
            }
#pragma unroll
            for (int mi = 0; mi < 2; mi++)
#pragma unroll
                for (int nj = 0; nj < 4; nj++) mma16h(acc[mi][nj], af[mi], bf[nj]);
        }
        __syncthreads();
    }

    float alpha = g_alpha[bh], bc = g_betac[bh];
#pragma unroll
    for (int mi = 0; mi < 2; mi++) {
        int r = qBase + wm * 32 + mi * 16 + lr;
#pragma unroll
        for (int nj = 0; nj < 4; nj++) {
            int d0 = wn * 32 + nj * 8 + lk * 2;
            float vs0 = g_vsum[bh * NHD + d0], vs1 = g_vsum[bh * NHD + d0 + 1];
            *(__half2*)&outh[(size_t)r * NHD + d0] =
                __floats2half2_rn(alpha * acc[mi][nj][0] + bc * vs0,
                                  alpha * acc[mi][nj][1] + bc * vs1);
            *(__half2*)&outh[(size_t)(r + 8) * NHD + d0] =
                __floats2half2_rn(alpha * acc[mi][nj][2] + bc * vs0,
                                  alpha * acc[mi][nj][3] + bc * vs1);
        }
    }
}

// ============ Kernel 7: projection fp16. final[co,t] = sum_c mid[t,c] W[co,c] + bias ============
__global__ __launch_bounds__(256) void proj_f16(const float* __restrict__ b_proj,
                                                float* __restrict__ outF) {
    int b = blockIdx.z;
    int coBase = blockIdx.y * 128;
    int tBase = blockIdx.x * 128;
    const __half* W = g_w16 + (size_t)3 * NC * NC;
    const __half* M = g_outh + (size_t)b * NT * NC;   // flat [t][c]

    __shared__ uint32_t As[128][20];
    __shared__ uint32_t Bs[128][20];

    int tid = threadIdx.x, lane = tid & 31, wid = tid >> 5;
    int wm = wid >> 2, wn = wid & 3;
    int lr = lane >> 2, lk = lane & 3;

    float acc[4][4][4];
#pragma unroll
    for (int mi = 0; mi < 4; mi++)
#pragma unroll
        for (int nj = 0; nj < 4; nj++)
#pragma unroll
            for (int ci = 0; ci < 4; ci++) acc[mi][nj][ci] = 0.f;

    for (int k0 = 0; k0 < NC; k0 += 32) {
#pragma unroll
        for (int i = 0; i < 2; i++) {
            int idx = tid + i * 256;
            int row = idx >> 2, uu = idx & 3;
            *(uint4*)&As[row][uu * 4] =
                *(const uint4*)&W[(size_t)(coBase + row) * NC + k0 + uu * 8];
            *(uint4*)&Bs[row][uu * 4] =
                *(const uint4*)&M[(size_t)(tBase + row) * NC + k0 + uu * 8];
        }
        __syncthreads();
#pragma unroll
        for (int ci = 0; ci < 2; ci++) {
            int kc = ci * 8;
            uint32_t af[4][4], bf[4][2];
#pragma unroll
            for (int mi = 0; mi < 4; mi++) {
                int m0 = wm * 64 + mi * 16 + lr;
                af[mi][0] = As[m0][kc + lk];
                af[mi][1] = As[m0 + 8][kc + lk];
                af[mi][2] = As[m0][kc + lk + 4];
                af[mi][3] = As[m0 + 8][kc + lk + 4];
            }
#pragma unroll
            for (int nj = 0; nj < 4; nj++) {
                int n0 = wn * 32 + nj * 8 + lr;
                bf[nj][0] = Bs[n0][kc + lk];
                bf[nj][1] = Bs[n0][kc + lk + 4];
            }
#pragma unroll
            for (int mi = 0; mi < 4; mi++)
#pragma unroll
                for (int nj = 0; nj < 4; nj++) mma16h(acc[mi][nj], af[mi], bf[nj]);
        }
        __syncthreads();
    }
#pragma unroll
    for (int mi = 0; mi < 4; mi++) {
        int co = coBase + wm * 64 + mi * 16 + lr;
        float bias0 = b_proj[co], bias1 = b_proj[co + 8];
        float* op0 = outF + (size_t)b * NC * NT + (size_t)co * NT;
        float* op1 = op0 + (size_t)8 * NT;
#pragma unroll
        for (int nj = 0; nj < 4; nj++) {
            int cc = tBase + wn * 32 + nj * 8 + lk * 2;
            *(float2*)&op0[cc] = make_float2(acc[mi][nj][0] + bias0, acc[mi][nj][1] + bias0);
            *(float2*)&op1[cc] = make_float2(acc[mi][nj][2] + bias1, acc[mi][nj][3] + bias1);
        }
    }
}

// ---------------- launch ----------------
extern "C" void kernel_launch(void* const* d_in, const int* in_sizes, int n_in,
                              void* d_out, int out_size) {
    (void)in_sizes; (void)n_in; (void)out_size;
    const float* x        = (const float*)d_in[0];
    const float* w_q      = (const float*)d_in[1];
    const float* w_k      = (const float*)d_in[2];
    const float* w_v      = (const float*)d_in[3];
    const float* w_head   = (const float*)d_in[4];
    const float* in_gamma = (const float*)d_in[5];
    const float* in_beta  = (const float*)d_in[6];
    const float* w_proj   = (const float*)d_in[7];
    const float* b_proj   = (const float*)d_in[8];
    float* outF = (float*)d_out;

    prep_w<<<4096, 256>>>(w_q, w_k, w_v, w_proj);
    prep_x<<<dim3(32, 16, 4), dim3(32, 8)>>>(x);
    qkv_f16<<<dim3(8, 4, 12), 256>>>();
    qk_f16<<<dim3(8, 8, 32), 256>>>();
    mixsm_kernel<<<dim3(1024, 4), 256>>>(w_head);
    vsum_f16<<<2048, 256>>>();
    finalize_kernel<<<32, 256>>>(in_gamma, in_beta);
    av_fp16<<<dim3(8, 32), 256>>>();
    proj_f16<<<dim3(8, 4, 4), 256>>>(b_proj, outF);
}